// round 1
// baseline (speedup 1.0000x reference)
#include <cuda_runtime.h>
#include <math.h>

#define D_MODEL 512
#define N_HEADS 8
#define HD      64
#define BATCH   2
#define SEQ     4096
#define MROWS   (BATCH * SEQ)   // 8192

// Scratch (static device arrays; no allocation in kernel_launch)
__device__ float g_QT[D_MODEL * MROWS];   // Q transposed: [n=512][m=8192]
__device__ float g_KT[D_MODEL * MROWS];   // K transposed: [n=512][m=8192]
__device__ float g_V [MROWS * D_MODEL];   // V natural:    [m=8192][n=512]
__device__ float g_attn[MROWS * D_MODEL]; // attn natural: [m=8192][n=512]

// ---------------------------------------------------------------------------
// GEMM: C[M,N] = A[M,K] @ B[K,N] + bias ; M=8192, N=K=512
// trans_out = 0 : C stored row-major [M][N]
// trans_out = 1 : C stored column-major [N][M] (for Q/K attention layout)
// Block tile 64x64, K-tile 16, 256 threads, 4x4 micro-tile.
// ---------------------------------------------------------------------------
__global__ __launch_bounds__(256) void gemm_kernel(
    const float* __restrict__ A, const float* __restrict__ B,
    const float* __restrict__ bias, float* __restrict__ C, int trans_out)
{
    const int M = MROWS, N = D_MODEL, K = D_MODEL;
    __shared__ float As[16][64];   // [k][m]  (A tile transposed in smem)
    __shared__ float Bs[16][64];   // [k][n]

    int tid = threadIdx.x;
    int tx = tid & 15, ty = tid >> 4;
    int bm = blockIdx.y * 64, bn = blockIdx.x * 64;

    // global load mapping
    int a_row = tid >> 2;      // 0..63
    int a_k4  = tid & 3;       // 0..3  (k offset = 4*a_k4)
    int b_row = tid >> 4;      // 0..15
    int b_c4  = tid & 15;      // 0..15

    float acc[4][4];
#pragma unroll
    for (int i = 0; i < 4; i++)
#pragma unroll
        for (int j = 0; j < 4; j++) acc[i][j] = 0.0f;

    const float* Aptr = A + (size_t)(bm + a_row) * K + a_k4 * 4;
    const float* Bptr = B + (size_t)b_row * N + bn + b_c4 * 4;

    for (int kt = 0; kt < K; kt += 16) {
        float4 av = *(const float4*)(Aptr + kt);
        float4 bv = *(const float4*)(Bptr + (size_t)kt * N);
        As[a_k4 * 4 + 0][a_row] = av.x;
        As[a_k4 * 4 + 1][a_row] = av.y;
        As[a_k4 * 4 + 2][a_row] = av.z;
        As[a_k4 * 4 + 3][a_row] = av.w;
        *(float4*)&Bs[b_row][b_c4 * 4] = bv;
        __syncthreads();

#pragma unroll
        for (int k = 0; k < 16; k++) {
            float4 a4 = *(const float4*)&As[k][ty * 4];
            float4 b4 = *(const float4*)&Bs[k][tx * 4];
            float av_[4] = {a4.x, a4.y, a4.z, a4.w};
            float bv_[4] = {b4.x, b4.y, b4.z, b4.w};
#pragma unroll
            for (int i = 0; i < 4; i++)
#pragma unroll
                for (int j = 0; j < 4; j++)
                    acc[i][j] = fmaf(av_[i], bv_[j], acc[i][j]);
        }
        __syncthreads();
    }

    if (!trans_out) {
#pragma unroll
        for (int i = 0; i < 4; i++) {
            int m = bm + ty * 4 + i;
            int c = bn + tx * 4;
            float4 bb = *(const float4*)&bias[c];
            float4 v;
            v.x = acc[i][0] + bb.x;
            v.y = acc[i][1] + bb.y;
            v.z = acc[i][2] + bb.z;
            v.w = acc[i][3] + bb.w;
            *(float4*)&C[(size_t)m * N + c] = v;
        }
    } else {
#pragma unroll
        for (int j = 0; j < 4; j++) {
            int n = bn + tx * 4 + j;
            float bj = bias[n];
            float4 v;
            v.x = acc[0][j] + bj;
            v.y = acc[1][j] + bj;
            v.z = acc[2][j] + bj;
            v.w = acc[3][j] + bj;
            *(float4*)&C[(size_t)n * M + bm + ty * 4] = v;
        }
    }
}

// ---------------------------------------------------------------------------
// Flash attention (fp32, non-causal).
// Grid: (SEQ/64, H, B), 256 threads. Q-tile 64, K-tile 64, hd = 64.
// Q/K read from transposed layout [n][m] -> smem [d][r]/[d][k] conflict-free.
// Online softmax per 4 owned query rows; P^T staged in stride-65 smem.
// ---------------------------------------------------------------------------
__global__ __launch_bounds__(256) void flash_kernel(
    const float* __restrict__ QT, const float* __restrict__ KT,
    const float* __restrict__ V, float* __restrict__ O)
{
    extern __shared__ float sm[];
    float (*Qs)[64] = (float(*)[64])(sm);               // [d][r]
    float (*Ks)[64] = (float(*)[64])(sm + 64 * 64);     // [d][k]
    float (*Vs)[64] = (float(*)[64])(sm + 2 * 64 * 64); // [k][d]
    float (*Ps)[65] = (float(*)[65])(sm + 3 * 64 * 64); // [k][r], stride 65

    const int M = MROWS;
    int b = blockIdx.z, h = blockIdx.y;
    int q0 = blockIdx.x * 64;
    int tid = threadIdx.x, tx = tid & 15, ty = tid >> 4;

    const float scale = 0.125f; // 1/sqrt(64), folded into Q at load

    // Load Q tile (scaled)
#pragma unroll
    for (int i = 0; i < 4; i++) {
        int lin = tid + i * 256;           // 0..1023 float4 slots
        int d = lin >> 4, r4 = lin & 15;
        float4 v = *(const float4*)&QT[(size_t)(h * HD + d) * M + b * SEQ + q0 + r4 * 4];
        v.x *= scale; v.y *= scale; v.z *= scale; v.w *= scale;
        *(float4*)&Qs[d][r4 * 4] = v;
    }

    float mi[4], li[4], o[4][4];
#pragma unroll
    for (int i = 0; i < 4; i++) {
        mi[i] = -1e30f;
        li[i] = 0.0f;
#pragma unroll
        for (int j = 0; j < 4; j++) o[i][j] = 0.0f;
    }

    for (int j0 = 0; j0 < SEQ; j0 += 64) {
        // Load K tile [d][k] and V tile [k][d]
#pragma unroll
        for (int i = 0; i < 4; i++) {
            int lin = tid + i * 256;
            int d = lin >> 4, r4 = lin & 15;
            *(float4*)&Ks[d][r4 * 4] =
                *(const float4*)&KT[(size_t)(h * HD + d) * M + b * SEQ + j0 + r4 * 4];
            *(float4*)&Vs[d][r4 * 4] =
                *(const float4*)&V[(size_t)(b * SEQ + j0 + d) * D_MODEL + h * HD + r4 * 4];
        }
        __syncthreads();

        // S = (scaled Q)^T K : rows 4ty+i (queries), cols 4tx+j (keys)
        float s[4][4];
#pragma unroll
        for (int i = 0; i < 4; i++)
#pragma unroll
            for (int j = 0; j < 4; j++) s[i][j] = 0.0f;

#pragma unroll 8
        for (int d = 0; d < 64; d++) {
            float4 a4 = *(const float4*)&Qs[d][ty * 4];
            float4 b4 = *(const float4*)&Ks[d][tx * 4];
            float av_[4] = {a4.x, a4.y, a4.z, a4.w};
            float bv_[4] = {b4.x, b4.y, b4.z, b4.w};
#pragma unroll
            for (int i = 0; i < 4; i++)
#pragma unroll
                for (int j = 0; j < 4; j++)
                    s[i][j] = fmaf(av_[i], bv_[j], s[i][j]);
        }

        // Online softmax over this key tile (reduce across the 16 tx lanes)
#pragma unroll
        for (int i = 0; i < 4; i++) {
            float mx = fmaxf(fmaxf(s[i][0], s[i][1]), fmaxf(s[i][2], s[i][3]));
            mx = fmaxf(mx, __shfl_xor_sync(0xffffffffu, mx, 1));
            mx = fmaxf(mx, __shfl_xor_sync(0xffffffffu, mx, 2));
            mx = fmaxf(mx, __shfl_xor_sync(0xffffffffu, mx, 4));
            mx = fmaxf(mx, __shfl_xor_sync(0xffffffffu, mx, 8));
            float mnew = fmaxf(mi[i], mx);
            float alpha = __expf(mi[i] - mnew);
            mi[i] = mnew;
            float rs = 0.0f;
#pragma unroll
            for (int j = 0; j < 4; j++) {
                float p = __expf(s[i][j] - mnew);
                s[i][j] = p;
                rs += p;
            }
            rs += __shfl_xor_sync(0xffffffffu, rs, 1);
            rs += __shfl_xor_sync(0xffffffffu, rs, 2);
            rs += __shfl_xor_sync(0xffffffffu, rs, 4);
            rs += __shfl_xor_sync(0xffffffffu, rs, 8);
            li[i] = li[i] * alpha + rs;
#pragma unroll
            for (int j = 0; j < 4; j++) o[i][j] *= alpha;
        }

        // Stage P^T (stride-65 -> <=2-way store conflicts)
#pragma unroll
        for (int i = 0; i < 4; i++)
#pragma unroll
            for (int j = 0; j < 4; j++)
                Ps[tx * 4 + j][ty * 4 + i] = s[i][j];
        __syncthreads();

        // O += P V : rows 4ty+i (queries), cols 4tx+j (dims)
#pragma unroll 8
        for (int k = 0; k < 64; k++) {
            float a0 = Ps[k][ty * 4 + 0];
            float a1 = Ps[k][ty * 4 + 1];
            float a2 = Ps[k][ty * 4 + 2];
            float a3 = Ps[k][ty * 4 + 3];
            float4 b4 = *(const float4*)&Vs[k][tx * 4];
            float bv_[4] = {b4.x, b4.y, b4.z, b4.w};
            float av_[4] = {a0, a1, a2, a3};
#pragma unroll
            for (int i = 0; i < 4; i++)
#pragma unroll
                for (int j = 0; j < 4; j++)
                    o[i][j] = fmaf(av_[i], bv_[j], o[i][j]);
        }
        __syncthreads();
    }

    // Normalize and store to attn (natural [B*S][D], head columns)
#pragma unroll
    for (int i = 0; i < 4; i++) {
        float inv = 1.0f / li[i];
        float4 v;
        v.x = o[i][0] * inv;
        v.y = o[i][1] * inv;
        v.z = o[i][2] * inv;
        v.w = o[i][3] * inv;
        *(float4*)&O[(size_t)(b * SEQ + q0 + ty * 4 + i) * D_MODEL + h * HD + tx * 4] = v;
    }
}

// ---------------------------------------------------------------------------
extern "C" void kernel_launch(void* const* d_in, const int* in_sizes, int n_in,
                              void* d_out, int out_size)
{
    const float* x  = (const float*)d_in[0];
    const float* Wq = (const float*)d_in[1];
    const float* bq = (const float*)d_in[2];
    const float* Wk = (const float*)d_in[3];
    const float* bk = (const float*)d_in[4];
    const float* Wv = (const float*)d_in[5];
    const float* bv = (const float*)d_in[6];
    const float* Wo = (const float*)d_in[7];
    const float* bo = (const float*)d_in[8];
    float* out = (float*)d_out;

    float *QT, *KT, *Vb, *attn;
    cudaGetSymbolAddress((void**)&QT,   g_QT);
    cudaGetSymbolAddress((void**)&KT,   g_KT);
    cudaGetSymbolAddress((void**)&Vb,   g_V);
    cudaGetSymbolAddress((void**)&attn, g_attn);

    const int smem_flash = (3 * 64 * 64 + 64 * 65) * (int)sizeof(float); // 65792 B
    cudaFuncSetAttribute(flash_kernel,
                         cudaFuncAttributeMaxDynamicSharedMemorySize, smem_flash);

    dim3 ggrid(D_MODEL / 64, MROWS / 64);   // (8, 128)
    gemm_kernel<<<ggrid, 256>>>(x, Wq, bq, QT, 1);
    gemm_kernel<<<ggrid, 256>>>(x, Wk, bk, KT, 1);
    gemm_kernel<<<ggrid, 256>>>(x, Wv, bv, Vb, 0);

    dim3 fgrid(SEQ / 64, N_HEADS, BATCH);   // (64, 8, 2)
    flash_kernel<<<fgrid, 256, smem_flash>>>(QT, KT, Vb, attn);

    gemm_kernel<<<ggrid, 256>>>(attn, Wo, bo, out, 0);
}